// round 12
// baseline (speedup 1.0000x reference)
#include <cuda_runtime.h>
#include <cuda_bf16.h>
#include <math.h>
#include <stdint.h>

#define N_NODES 12000
#define N_EDGES 384000
#define FIN_    128
#define DD      64
#define BUF     (N_NODES * DD)   // 768000

// Scratch (no allocation allowed)
__device__ float  g_fsc[9 * BUF + N_NODES];
__device__ int    g_isc[N_NODES + (N_NODES + 1) + N_NODES + N_EDGES];
__device__ double g_sums[384];   // 3 layers x (64 sum + 64 sumsq)

// ---------------- graph prep ----------------
__global__ void zero_all_kernel(int* cnt, double* sums) {
    int i = blockIdx.x * 256 + threadIdx.x;
    if (i < N_NODES) cnt[i] = 0;
    if (i < 384) sums[i] = 0.0;
}

__global__ void hist_kernel(const int* __restrict__ dst, int* cnt) {
    int i = blockIdx.x * 256 + threadIdx.x;
    atomicAdd(&cnt[dst[i]], 1);
}

// shfl-based scan: 2 barriers instead of a 10-step ladder (was 23us, 1 block)
__global__ void scan_kernel(const int* __restrict__ cnt, int* __restrict__ off,
                            int* __restrict__ cur, float* __restrict__ dis) {
    __shared__ int wsum[32];
    const int C = 12;                        // 1024*12 = 12288 >= 12000
    int tid = threadIdx.x;
    int lane = tid & 31, wid = tid >> 5;
    int base = tid * C;
    int loc[C];
    int s = 0;
#pragma unroll
    for (int j = 0; j < C; j++) {
        int i = base + j;
        int v = (i < N_NODES) ? cnt[i] : 0;
        loc[j] = v; s += v;
    }
    // inclusive scan of per-thread sums within warp
    int ps = s;
#pragma unroll
    for (int d = 1; d < 32; d <<= 1) {
        int t = __shfl_up_sync(0xffffffff, ps, d);
        if (lane >= d) ps += t;
    }
    if (lane == 31) wsum[wid] = ps;
    __syncthreads();
    if (wid == 0) {
        int w = wsum[lane];
        int pw = w;
#pragma unroll
        for (int d = 1; d < 32; d <<= 1) {
            int t = __shfl_up_sync(0xffffffff, pw, d);
            if (lane >= d) pw += t;
        }
        wsum[lane] = pw - w;                 // exclusive warp base
    }
    __syncthreads();
    int run = wsum[wid] + ps - s;            // exclusive prefix for this thread
#pragma unroll
    for (int j = 0; j < C; j++) {
        int i = base + j;
        if (i < N_NODES) {
            off[i] = run; cur[i] = run;
            dis[i] = rsqrtf((float)(loc[j] + 1));
            run += loc[j];
        }
    }
    if (tid == 1023) off[N_NODES] = run;
}

__global__ void fill_kernel(const int* __restrict__ src, const int* __restrict__ dst,
                            int* cur, int* __restrict__ csr) {
    int i = blockIdx.x * 256 + threadIdx.x;
    int p = atomicAdd(&cur[dst[i]], 1);
    csr[p] = src[i];
}

// ---------------- small GEMM ----------------
// EPI 1: leaky_relu(v + aux[col]); EPI 2: v + aux[col]; EPI 3: plain v
template <int FIN, int NOUT, int EPI>
__global__ void gemm_kernel(const float* __restrict__ X, const float* __restrict__ W,
                            const float* __restrict__ aux, float* __restrict__ Y) {
    __shared__ float xs[16 * FIN];
    int tid = threadIdx.x;
    int rowbase = blockIdx.x * 16;
    const float4* Xg = (const float4*)(X + (size_t)rowbase * FIN);
    float4* xs4 = (float4*)xs;
#pragma unroll
    for (int u = tid; u < 16 * FIN / 4; u += 256) xs4[u] = Xg[u];
    __syncthreads();

    const int LANES = 256 / NOUT;
    const int RPT   = 16 / LANES;
    int col = tid % NOUT;
    int rl  = tid / NOUT;
    float acc[RPT];
#pragma unroll
    for (int r = 0; r < RPT; r++) acc[r] = 0.f;

#pragma unroll 4
    for (int k = 0; k < FIN; k++) {
        float w = __ldg(&W[k * NOUT + col]);
#pragma unroll
        for (int r = 0; r < RPT; r++)
            acc[r] += xs[(rl * RPT + r) * FIN + k] * w;
    }
#pragma unroll
    for (int r = 0; r < RPT; r++) {
        int row = rowbase + rl * RPT + r;
        float v = acc[r];
        if (EPI == 1 || EPI == 2) {
            v += aux[col];
            if (EPI == 1) v = (v > 0.f) ? v : 0.01f * v;
        }
        Y[(size_t)row * NOUT + col] = v;
    }
}

// ---- gather + bias + sigmoid: h unscaled; dis applied per-edge (4-unroll) --
__global__ void gather_sig_kernel(const float* __restrict__ hs, const float* __restrict__ dis,
                                  const int* __restrict__ off, const int* __restrict__ csr,
                                  const float* __restrict__ bias, float* __restrict__ sbuf) {
    int warp = (blockIdx.x * 256 + threadIdx.x) >> 5;
    int lane = threadIdx.x & 31;
    const float2* h2 = (const float2*)hs;
    float dd = dis[warp];
    float2 self = h2[(size_t)warp * 32 + lane];
    float2 acc = make_float2(dd * self.x, dd * self.y);     // dis_d * h_d
    int e0 = off[warp], e1 = off[warp + 1];
    int e = e0;
    for (; e + 4 <= e1; e += 4) {
        int s0 = __ldg(&csr[e]);
        int s1 = __ldg(&csr[e + 1]);
        int s2 = __ldg(&csr[e + 2]);
        int s3 = __ldg(&csr[e + 3]);
        float d0 = __ldg(&dis[s0]);
        float d1 = __ldg(&dis[s1]);
        float d2 = __ldg(&dis[s2]);
        float d3 = __ldg(&dis[s3]);
        float2 v0 = h2[(size_t)s0 * 32 + lane];
        float2 v1 = h2[(size_t)s1 * 32 + lane];
        float2 v2 = h2[(size_t)s2 * 32 + lane];
        float2 v3 = h2[(size_t)s3 * 32 + lane];
        acc.x += d0 * v0.x + d1 * v1.x + d2 * v2.x + d3 * v3.x;
        acc.y += d0 * v0.y + d1 * v1.y + d2 * v2.y + d3 * v3.y;
    }
    for (; e < e1; e++) {
        int s0 = __ldg(&csr[e]);
        float d0 = __ldg(&dis[s0]);
        float2 v0 = h2[(size_t)s0 * 32 + lane];
        acc.x += d0 * v0.x;
        acc.y += d0 * v0.y;
    }
    float2 bb = ((const float2*)bias)[lane];
    float vx = dd * acc.x + bb.x;
    float vy = dd * acc.y + bb.y;
    vx = __fdividef(1.f, 1.f + __expf(-vx));
    vy = __fdividef(1.f, 1.f + __expf(-vy));
    ((float2*)sbuf)[(size_t)warp * 32 + lane] = make_float2(vx, vy);
}

// ---------------- BatchNorm ----------------
__global__ void stats_kernel(const float* __restrict__ sbuf, double* __restrict__ sums) {
    int tid = threadIdx.x;
    int c = tid & 63, rg = tid >> 6;
    double s = 0.0, s2 = 0.0;
    for (int row = blockIdx.x * 4 + rg; row < N_NODES; row += 64 * 4) {
        float v = sbuf[(size_t)row * 64 + c];
        s += v; s2 += (double)v * (double)v;
    }
    __shared__ double sh[256], sh2[256];
    sh[tid] = s; sh2[tid] = s2;
    __syncthreads();
    if (rg == 0) {
        s  = sh[tid]  + sh[tid + 64]  + sh[tid + 128]  + sh[tid + 192];
        s2 = sh2[tid] + sh2[tid + 64] + sh2[tid + 128] + sh2[tid + 192];
        atomicAdd(&sums[c], s);
        atomicAdd(&sums[64 + c], s2);
    }
}

__global__ void bn_apply_kernel(const float* __restrict__ sbuf, const double* __restrict__ sums,
                                const float* __restrict__ gamma, const float* __restrict__ beta,
                                float* __restrict__ out) {
    int idx = blockIdx.x * 256 + threadIdx.x;
    int c = idx & 63;
    double mu  = sums[c] * (1.0 / N_NODES);
    double var = sums[64 + c] * (1.0 / N_NODES) - mu * mu;
    float inv = rsqrtf((float)var + 1e-4f);
    out[idx] = (float)((double)sbuf[idx] - mu) * inv * gamma[c] + beta[c];
}

// ------- z = noise * exp(bn(SBs)) + bn(SBm)  (BN of both branches fused) ----
__global__ void z_bn_kernel(const float* __restrict__ noise,
                            const float* __restrict__ SBm, const float* __restrict__ SBs,
                            const double* __restrict__ sums,
                            const float* __restrict__ gm, const float* __restrict__ bem,
                            const float* __restrict__ gs, const float* __restrict__ bes,
                            float* __restrict__ z) {
    int idx = blockIdx.x * 256 + threadIdx.x;
    int c = idx & 63;
    const double INVN = 1.0 / N_NODES;
    double mum = sums[128 + c] * INVN;
    double varm = sums[128 + 64 + c] * INVN - mum * mum;
    float am = rsqrtf((float)varm + 1e-4f) * gm[c];
    float zm = (float)((double)SBm[idx] - mum) * am + bem[c];
    double mus = sums[256 + c] * INVN;
    double vars = sums[256 + 64 + c] * INVN - mus * mus;
    float as = rsqrtf((float)vars + 1e-4f) * gs[c];
    float zs = (float)((double)SBs[idx] - mus) * as + bes[c];
    z[idx] = noise[idx] * expf(zs) + zm;
}

// ====== A_pred = sigmoid(z @ z^T) via mma.sync bf16 two-term split ==========
// (R4/R8-proven configuration: full grid, direct coalesced float2 stores)
#define TPITCH 72   // bf16 elements per smem row (144 bytes)

__device__ __forceinline__ void mma_bf16(float* c, const uint32_t* a, const uint32_t* b) {
    asm volatile(
        "mma.sync.aligned.m16n8k16.row.col.f32.bf16.bf16.f32 "
        "{%0,%1,%2,%3}, {%4,%5,%6,%7}, {%8,%9}, {%0,%1,%2,%3};"
        : "+f"(c[0]), "+f"(c[1]), "+f"(c[2]), "+f"(c[3])
        : "r"(a[0]), "r"(a[1]), "r"(a[2]), "r"(a[3]), "r"(b[0]), "r"(b[1]));
}

__global__ void __launch_bounds__(256, 2)
apred_mma_kernel(const float* __restrict__ z, float* __restrict__ out) {
    extern __shared__ __nv_bfloat16 sm[];
    __nv_bfloat16* Ahi = sm;
    __nv_bfloat16* Alo = sm + 128 * TPITCH;
    __nv_bfloat16* Bhi = sm + 2 * 128 * TPITCH;
    __nv_bfloat16* Blo = sm + 3 * 128 * TPITCH;

    int tid = threadIdx.x;
    int row0 = blockIdx.y * 128, col0 = blockIdx.x * 128;

    // ---- fill: split z rows into bf16 hi/lo ----
    for (int u = tid; u < 2048; u += 256) {
        int r = u >> 4, f4 = u & 15;
        int gr = row0 + r;
        float4 v = make_float4(0.f, 0.f, 0.f, 0.f);
        if (gr < N_NODES) v = *(const float4*)(z + (size_t)gr * 64 + f4 * 4);
        {
            __nv_bfloat16 h0 = __float2bfloat16_rn(v.x), h1 = __float2bfloat16_rn(v.y);
            __nv_bfloat16 h2 = __float2bfloat16_rn(v.z), h3 = __float2bfloat16_rn(v.w);
            __nv_bfloat16 l0 = __float2bfloat16_rn(v.x - __bfloat162float(h0));
            __nv_bfloat16 l1 = __float2bfloat16_rn(v.y - __bfloat162float(h1));
            __nv_bfloat16 l2 = __float2bfloat16_rn(v.z - __bfloat162float(h2));
            __nv_bfloat16 l3 = __float2bfloat16_rn(v.w - __bfloat162float(h3));
            int e = r * TPITCH + f4 * 4;
            *(uint32_t*)&Ahi[e]     = ((uint32_t)__bfloat16_as_ushort(h1) << 16) | __bfloat16_as_ushort(h0);
            *(uint32_t*)&Ahi[e + 2] = ((uint32_t)__bfloat16_as_ushort(h3) << 16) | __bfloat16_as_ushort(h2);
            *(uint32_t*)&Alo[e]     = ((uint32_t)__bfloat16_as_ushort(l1) << 16) | __bfloat16_as_ushort(l0);
            *(uint32_t*)&Alo[e + 2] = ((uint32_t)__bfloat16_as_ushort(l3) << 16) | __bfloat16_as_ushort(l2);
        }
        int gc = col0 + r;
        float4 w = make_float4(0.f, 0.f, 0.f, 0.f);
        if (gc < N_NODES) w = *(const float4*)(z + (size_t)gc * 64 + f4 * 4);
        {
            __nv_bfloat16 h0 = __float2bfloat16_rn(w.x), h1 = __float2bfloat16_rn(w.y);
            __nv_bfloat16 h2 = __float2bfloat16_rn(w.z), h3 = __float2bfloat16_rn(w.w);
            __nv_bfloat16 l0 = __float2bfloat16_rn(w.x - __bfloat162float(h0));
            __nv_bfloat16 l1 = __float2bfloat16_rn(w.y - __bfloat162float(h1));
            __nv_bfloat16 l2 = __float2bfloat16_rn(w.z - __bfloat162float(h2));
            __nv_bfloat16 l3 = __float2bfloat16_rn(w.w - __bfloat162float(h3));
            int e = r * TPITCH + f4 * 4;
            *(uint32_t*)&Bhi[e]     = ((uint32_t)__bfloat16_as_ushort(h1) << 16) | __bfloat16_as_ushort(h0);
            *(uint32_t*)&Bhi[e + 2] = ((uint32_t)__bfloat16_as_ushort(h3) << 16) | __bfloat16_as_ushort(h2);
            *(uint32_t*)&Blo[e]     = ((uint32_t)__bfloat16_as_ushort(l1) << 16) | __bfloat16_as_ushort(l0);
            *(uint32_t*)&Blo[e + 2] = ((uint32_t)__bfloat16_as_ushort(l3) << 16) | __bfloat16_as_ushort(l2);
        }
    }
    __syncthreads();

    int wid = tid >> 5, lane = tid & 31;
    int gid = lane >> 2, tig = lane & 3;
    int m0 = (wid & 3) * 32;
    int n0 = (wid >> 2) * 64;

    float acc[2][8][4];
#pragma unroll
    for (int h = 0; h < 2; h++)
#pragma unroll
        for (int nb = 0; nb < 8; nb++)
#pragma unroll
            for (int q = 0; q < 4; q++) acc[h][nb][q] = 0.f;

#pragma unroll
    for (int p = 0; p < 3; p++) {
        const __nv_bfloat16* Ap = (p == 2) ? Alo : Ahi;
        const __nv_bfloat16* Bp = (p == 1) ? Blo : Bhi;
#pragma unroll
        for (int ks = 0; ks < 4; ks++) {
            int k0 = ks * 16;
            uint32_t a[2][4];
#pragma unroll
            for (int h = 0; h < 2; h++) {
                int r = m0 + 16 * h + gid;
                int e = r * TPITCH + k0 + 2 * tig;
                a[h][0] = *(const uint32_t*)&Ap[e];
                a[h][1] = *(const uint32_t*)&Ap[e + 8 * TPITCH];
                a[h][2] = *(const uint32_t*)&Ap[e + 8];
                a[h][3] = *(const uint32_t*)&Ap[e + 8 * TPITCH + 8];
            }
#pragma unroll
            for (int nb = 0; nb < 8; nb++) {
                int nr = n0 + 8 * nb + gid;
                int e = nr * TPITCH + k0 + 2 * tig;
                uint32_t b[2];
                b[0] = *(const uint32_t*)&Bp[e];
                b[1] = *(const uint32_t*)&Bp[e + 8];
                mma_bf16(acc[0][nb], a[0], b);
                mma_bf16(acc[1][nb], a[1], b);
            }
        }
    }

    // ---- epilogue: sigmoid + guarded float2 stores (32B per quad) ----
#pragma unroll
    for (int h = 0; h < 2; h++) {
#pragma unroll
        for (int nb = 0; nb < 8; nb++) {
            float* q = acc[h][nb];
            int r0 = row0 + m0 + 16 * h + gid;
            int c  = col0 + n0 + 8 * nb + 2 * tig;
            if (c < N_NODES) {
                if (r0 < N_NODES) {
                    float2 v;
                    v.x = __fdividef(1.f, 1.f + __expf(-q[0]));
                    v.y = __fdividef(1.f, 1.f + __expf(-q[1]));
                    *(float2*)(out + (size_t)r0 * N_NODES + c) = v;
                }
                int r1 = r0 + 8;
                if (r1 < N_NODES) {
                    float2 v;
                    v.x = __fdividef(1.f, 1.f + __expf(-q[2]));
                    v.y = __fdividef(1.f, 1.f + __expf(-q[3]));
                    *(float2*)(out + (size_t)r1 * N_NODES + c) = v;
                }
            }
        }
    }
}

// ---------------- launch -----------------------------------------------------
extern "C" void kernel_launch(void* const* d_in, const int* in_sizes, int n_in,
                              void* d_out, int out_size) {
    const float* x     = (const float*)d_in[0];
    const int*   src   = (const int*)  d_in[1];
    const int*   dst   = (const int*)  d_in[2];
    const float* noise = (const float*)d_in[4];
    const float* W0  = (const float*)d_in[5];
    const float* b0  = (const float*)d_in[6];
    const float* g0  = (const float*)d_in[7];
    const float* be0 = (const float*)d_in[8];
    const float* Wm  = (const float*)d_in[9];
    const float* bm  = (const float*)d_in[10];
    const float* gm  = (const float*)d_in[11];
    const float* bem = (const float*)d_in[12];
    const float* Ws  = (const float*)d_in[13];
    const float* bs  = (const float*)d_in[14];
    const float* gs  = (const float*)d_in[15];
    const float* bes = (const float*)d_in[16];
    const float* Dw1 = (const float*)d_in[17];
    const float* Db1 = (const float*)d_in[18];
    const float* Dw2 = (const float*)d_in[19];
    const float* Db2 = (const float*)d_in[20];
    float* out = (float*)d_out;

    float* fsc; int* isc; double* sums;
    cudaGetSymbolAddress((void**)&fsc, g_fsc);
    cudaGetSymbolAddress((void**)&isc, g_isc);
    cudaGetSymbolAddress((void**)&sums, g_sums);

    float* HSA  = fsc + 0 * BUF;
    float* HSB  = fsc + 1 * BUF;
    float* SB1  = fsc + 2 * BUF;
    float* SB2  = fsc + 3 * BUF;
    float* SB3  = fsc + 4 * BUF;
    float* HID  = fsc + 5 * BUF;
    float* Z    = fsc + 8 * BUF;
    float* DIS  = fsc + 9 * BUF;
    float* H1   = fsc + 0 * BUF;   // HSA dead by decoder time
    int* CNT = isc;
    int* OFF = CNT + N_NODES;
    int* CUR = OFF + N_NODES + 1;
    int* CSR = CUR + N_NODES;

    // static streams/events (host objects only; created once)
    static cudaStream_t s1 = nullptr, s2 = nullptr;
    static cudaEvent_t evA = nullptr, evB = nullptr, evC = nullptr, evD = nullptr, evE = nullptr;
    if (!s1) {
        cudaStreamCreateWithFlags(&s1, cudaStreamNonBlocking);
        cudaStreamCreateWithFlags(&s2, cudaStreamNonBlocking);
        cudaEventCreateWithFlags(&evA, cudaEventDisableTiming);
        cudaEventCreateWithFlags(&evB, cudaEventDisableTiming);
        cudaEventCreateWithFlags(&evC, cudaEventDisableTiming);
        cudaEventCreateWithFlags(&evD, cudaEventDisableTiming);
        cudaEventCreateWithFlags(&evE, cudaEventDisableTiming);
    }

    const int APRED_SMEM = 4 * 128 * TPITCH * 2;   // 73728 bytes
    cudaFuncSetAttribute(apred_mma_kernel, cudaFuncAttributeMaxDynamicSharedMemorySize, APRED_SMEM);

    // fork at graph start: gemm1 (no deps — unscaled) on s1, prep chain on main
    cudaEventRecord(evA, 0);
    cudaStreamWaitEvent(s1, evA, 0);
    gemm_kernel<FIN_, DD, 3><<<750, 256, 0, s1>>>(x, W0, nullptr, HSA);
    cudaEventRecord(evB, s1);

    zero_all_kernel<<<47, 256>>>(CNT, sums);
    hist_kernel<<<1500, 256>>>(dst, CNT);
    scan_kernel<<<1, 1024>>>(CNT, OFF, CUR, DIS);
    fill_kernel<<<1500, 256>>>(src, dst, CUR, CSR);
    cudaStreamWaitEvent(0, evB, 0);                 // join: gather1 needs HSA + CSR

    // layer 1
    gather_sig_kernel<<<1500, 256>>>(HSA, DIS, OFF, CSR, b0, SB1);
    stats_kernel<<<64, 256>>>(SB1, sums);
    bn_apply_kernel<<<3000, 256>>>(SB1, sums, g0, be0, HID);

    // fork: mean branch on main, logstd branch on s2 (both end at stats)
    cudaEventRecord(evC, 0);
    cudaStreamWaitEvent(s2, evC, 0);

    gemm_kernel<DD, DD, 3><<<750, 256>>>(HID, Wm, nullptr, HSA);
    gather_sig_kernel<<<1500, 256>>>(HSA, DIS, OFF, CSR, bm, SB2);
    stats_kernel<<<64, 256>>>(SB2, sums + 128);

    gemm_kernel<DD, DD, 3><<<750, 256, 0, s2>>>(HID, Ws, nullptr, HSB);
    gather_sig_kernel<<<1500, 256, 0, s2>>>(HSB, DIS, OFF, CSR, bs, SB3);
    stats_kernel<<<64, 256, 0, s2>>>(SB3, sums + 256);
    cudaEventRecord(evD, s2);
    cudaStreamWaitEvent(0, evD, 0);                 // join before z

    // z = noise*exp(bn(SB3)) + bn(SB2)   (both BNs fused in)
    z_bn_kernel<<<3000, 256>>>(noise, SB2, SB3, sums, gm, bem, gs, bes, Z);

    // fork: decoder on s1 concurrent with apred on main (disjoint out regions)
    cudaEventRecord(evA, 0);
    cudaStreamWaitEvent(s1, evA, 0);
    gemm_kernel<DD, DD, 1><<<750, 256, 0, s1>>>(Z, Dw1, Db1, H1);
    gemm_kernel<DD, FIN_, 2><<<750, 256, 0, s1>>>(H1, Dw2, Db2, out);
    cudaEventRecord(evE, s1);

    dim3 grid((N_NODES + 127) / 128, (N_NODES + 127) / 128);
    apred_mma_kernel<<<grid, 256, APRED_SMEM>>>(Z, out + (size_t)N_NODES * FIN_);
    cudaStreamWaitEvent(0, evE, 0);                 // final join
}

// round 14
// speedup vs baseline: 1.0291x; 1.0291x over previous
#include <cuda_runtime.h>
#include <cuda_bf16.h>
#include <math.h>
#include <stdint.h>

#define N_NODES 12000
#define N_EDGES 384000
#define FIN_    128
#define DD      64
#define BUF     (N_NODES * DD)   // 768000

// Scratch (no allocation allowed)
__device__ float  g_fsc[9 * BUF + N_NODES];
// layout: CNT[12000] | OFF[12016 incl. pad => CUR 16B-aligned] | CUR[12000] | CSR[384000]
__device__ int    g_isc[N_NODES + (N_NODES + 16) + N_NODES + N_EDGES];
__device__ double g_sums[384];   // 3 layers x (64 sum + 64 sumsq)

// ---------------- graph prep ----------------
__global__ void zero_all_kernel(int* cnt, double* sums) {
    int i = blockIdx.x * 256 + threadIdx.x;
    if (i < N_NODES) cnt[i] = 0;
    if (i < 384) sums[i] = 0.0;
}

__global__ void hist_kernel(const int* __restrict__ dst, int* cnt) {
    int i = blockIdx.x * 256 + threadIdx.x;
    atomicAdd(&cnt[dst[i]], 1);
}

// shfl scan + fully vectorized int4/float4 memory (prior scalar version was
// L1-wavefront-bound at ~22us; sync structure was never the cost)
__global__ void scan_kernel(const int* __restrict__ cnt, int* __restrict__ off,
                            int* __restrict__ cur, float* __restrict__ dis) {
    __shared__ int wsum[32];
    const int C = 12;                        // 1000 threads * 12 = 12000 exact
    int tid = threadIdx.x;
    int lane = tid & 31, wid = tid >> 5;
    int base = tid * C;
    bool live = (tid < N_NODES / C);         // tid < 1000: full int4x3 vectors
    int loc[C];
    int s = 0;
    if (live) {
        const int4* c4 = (const int4*)(cnt + base);
        int4 a = c4[0], b = c4[1], c = c4[2];
        loc[0] = a.x; loc[1] = a.y; loc[2]  = a.z; loc[3]  = a.w;
        loc[4] = b.x; loc[5] = b.y; loc[6]  = b.z; loc[7]  = b.w;
        loc[8] = c.x; loc[9] = c.y; loc[10] = c.z; loc[11] = c.w;
#pragma unroll
        for (int j = 0; j < C; j++) s += loc[j];
    } else {
#pragma unroll
        for (int j = 0; j < C; j++) loc[j] = 0;
    }
    // inclusive scan of per-thread sums within warp
    int ps = s;
#pragma unroll
    for (int d = 1; d < 32; d <<= 1) {
        int t = __shfl_up_sync(0xffffffff, ps, d);
        if (lane >= d) ps += t;
    }
    if (lane == 31) wsum[wid] = ps;
    __syncthreads();
    if (wid == 0) {
        int w = wsum[lane];
        int pw = w;
#pragma unroll
        for (int d = 1; d < 32; d <<= 1) {
            int t = __shfl_up_sync(0xffffffff, pw, d);
            if (lane >= d) pw += t;
        }
        wsum[lane] = pw - w;                 // exclusive warp base
    }
    __syncthreads();
    int run = wsum[wid] + ps - s;            // exclusive prefix for this thread
    if (live) {
        int o[C];
        float dv[C];
#pragma unroll
        for (int j = 0; j < C; j++) {
            o[j] = run;
            dv[j] = rsqrtf((float)(loc[j] + 1));
            run += loc[j];
        }
        int4* o4 = (int4*)(off + base);
        int4* u4 = (int4*)(cur + base);
        float4* d4 = (float4*)(dis + base);
        o4[0] = make_int4(o[0], o[1], o[2],  o[3]);
        o4[1] = make_int4(o[4], o[5], o[6],  o[7]);
        o4[2] = make_int4(o[8], o[9], o[10], o[11]);
        u4[0] = make_int4(o[0], o[1], o[2],  o[3]);
        u4[1] = make_int4(o[4], o[5], o[6],  o[7]);
        u4[2] = make_int4(o[8], o[9], o[10], o[11]);
        d4[0] = make_float4(dv[0], dv[1], dv[2],  dv[3]);
        d4[1] = make_float4(dv[4], dv[5], dv[6],  dv[7]);
        d4[2] = make_float4(dv[8], dv[9], dv[10], dv[11]);
    }
    if (tid == 1023) off[N_NODES] = run;     // run == total for tid >= 1000
}

__global__ void fill_kernel(const int* __restrict__ src, const int* __restrict__ dst,
                            int* cur, int* __restrict__ csr) {
    int i = blockIdx.x * 256 + threadIdx.x;
    int p = atomicAdd(&cur[dst[i]], 1);
    csr[p] = src[i];
}

// ---------------- small GEMM ----------------
// EPI 1: leaky_relu(v + aux[col]); EPI 2: v + aux[col]; EPI 3: plain v
template <int FIN, int NOUT, int EPI>
__global__ void gemm_kernel(const float* __restrict__ X, const float* __restrict__ W,
                            const float* __restrict__ aux, float* __restrict__ Y) {
    __shared__ float xs[16 * FIN];
    int tid = threadIdx.x;
    int rowbase = blockIdx.x * 16;
    const float4* Xg = (const float4*)(X + (size_t)rowbase * FIN);
    float4* xs4 = (float4*)xs;
#pragma unroll
    for (int u = tid; u < 16 * FIN / 4; u += 256) xs4[u] = Xg[u];
    __syncthreads();

    const int LANES = 256 / NOUT;
    const int RPT   = 16 / LANES;
    int col = tid % NOUT;
    int rl  = tid / NOUT;
    float acc[RPT];
#pragma unroll
    for (int r = 0; r < RPT; r++) acc[r] = 0.f;

#pragma unroll 4
    for (int k = 0; k < FIN; k++) {
        float w = __ldg(&W[k * NOUT + col]);
#pragma unroll
        for (int r = 0; r < RPT; r++)
            acc[r] += xs[(rl * RPT + r) * FIN + k] * w;
    }
#pragma unroll
    for (int r = 0; r < RPT; r++) {
        int row = rowbase + rl * RPT + r;
        float v = acc[r];
        if (EPI == 1 || EPI == 2) {
            v += aux[col];
            if (EPI == 1) v = (v > 0.f) ? v : 0.01f * v;
        }
        Y[(size_t)row * NOUT + col] = v;
    }
}

// ---- gather + bias + sigmoid: h unscaled; dis applied per-edge (4-unroll) --
__global__ void gather_sig_kernel(const float* __restrict__ hs, const float* __restrict__ dis,
                                  const int* __restrict__ off, const int* __restrict__ csr,
                                  const float* __restrict__ bias, float* __restrict__ sbuf) {
    int warp = (blockIdx.x * 256 + threadIdx.x) >> 5;
    int lane = threadIdx.x & 31;
    const float2* h2 = (const float2*)hs;
    float dd = dis[warp];
    float2 self = h2[(size_t)warp * 32 + lane];
    float2 acc = make_float2(dd * self.x, dd * self.y);     // dis_d * h_d
    int e0 = off[warp], e1 = off[warp + 1];
    int e = e0;
    for (; e + 4 <= e1; e += 4) {
        int s0 = __ldg(&csr[e]);
        int s1 = __ldg(&csr[e + 1]);
        int s2 = __ldg(&csr[e + 2]);
        int s3 = __ldg(&csr[e + 3]);
        float d0 = __ldg(&dis[s0]);
        float d1 = __ldg(&dis[s1]);
        float d2 = __ldg(&dis[s2]);
        float d3 = __ldg(&dis[s3]);
        float2 v0 = h2[(size_t)s0 * 32 + lane];
        float2 v1 = h2[(size_t)s1 * 32 + lane];
        float2 v2 = h2[(size_t)s2 * 32 + lane];
        float2 v3 = h2[(size_t)s3 * 32 + lane];
        acc.x += d0 * v0.x + d1 * v1.x + d2 * v2.x + d3 * v3.x;
        acc.y += d0 * v0.y + d1 * v1.y + d2 * v2.y + d3 * v3.y;
    }
    for (; e < e1; e++) {
        int s0 = __ldg(&csr[e]);
        float d0 = __ldg(&dis[s0]);
        float2 v0 = h2[(size_t)s0 * 32 + lane];
        acc.x += d0 * v0.x;
        acc.y += d0 * v0.y;
    }
    float2 bb = ((const float2*)bias)[lane];
    float vx = dd * acc.x + bb.x;
    float vy = dd * acc.y + bb.y;
    vx = __fdividef(1.f, 1.f + __expf(-vx));
    vy = __fdividef(1.f, 1.f + __expf(-vy));
    ((float2*)sbuf)[(size_t)warp * 32 + lane] = make_float2(vx, vy);
}

// ---------------- BatchNorm ----------------
__global__ void stats_kernel(const float* __restrict__ sbuf, double* __restrict__ sums) {
    int tid = threadIdx.x;
    int c = tid & 63, rg = tid >> 6;
    double s = 0.0, s2 = 0.0;
    for (int row = blockIdx.x * 4 + rg; row < N_NODES; row += 64 * 4) {
        float v = sbuf[(size_t)row * 64 + c];
        s += v; s2 += (double)v * (double)v;
    }
    __shared__ double sh[256], sh2[256];
    sh[tid] = s; sh2[tid] = s2;
    __syncthreads();
    if (rg == 0) {
        s  = sh[tid]  + sh[tid + 64]  + sh[tid + 128]  + sh[tid + 192];
        s2 = sh2[tid] + sh2[tid + 64] + sh2[tid + 128] + sh2[tid + 192];
        atomicAdd(&sums[c], s);
        atomicAdd(&sums[64 + c], s2);
    }
}

__global__ void bn_apply_kernel(const float* __restrict__ sbuf, const double* __restrict__ sums,
                                const float* __restrict__ gamma, const float* __restrict__ beta,
                                float* __restrict__ out) {
    int idx = blockIdx.x * 256 + threadIdx.x;
    int c = idx & 63;
    double mu  = sums[c] * (1.0 / N_NODES);
    double var = sums[64 + c] * (1.0 / N_NODES) - mu * mu;
    float inv = rsqrtf((float)var + 1e-4f);
    out[idx] = (float)((double)sbuf[idx] - mu) * inv * gamma[c] + beta[c];
}

// ------- z = noise * exp(bn(SBs)) + bn(SBm)  (BN of both branches fused) ----
__global__ void z_bn_kernel(const float* __restrict__ noise,
                            const float* __restrict__ SBm, const float* __restrict__ SBs,
                            const double* __restrict__ sums,
                            const float* __restrict__ gm, const float* __restrict__ bem,
                            const float* __restrict__ gs, const float* __restrict__ bes,
                            float* __restrict__ z) {
    int idx = blockIdx.x * 256 + threadIdx.x;
    int c = idx & 63;
    const double INVN = 1.0 / N_NODES;
    double mum = sums[128 + c] * INVN;
    double varm = sums[128 + 64 + c] * INVN - mum * mum;
    float am = rsqrtf((float)varm + 1e-4f) * gm[c];
    float zm = (float)((double)SBm[idx] - mum) * am + bem[c];
    double mus = sums[256 + c] * INVN;
    double vars = sums[256 + 64 + c] * INVN - mus * mus;
    float as = rsqrtf((float)vars + 1e-4f) * gs[c];
    float zs = (float)((double)SBs[idx] - mus) * as + bes[c];
    z[idx] = noise[idx] * expf(zs) + zm;
}

// ====== A_pred = sigmoid(z @ z^T) via mma.sync bf16 two-term split ==========
// (R4/R8-proven configuration: full grid, direct coalesced float2 stores)
#define TPITCH 72   // bf16 elements per smem row (144 bytes)

__device__ __forceinline__ void mma_bf16(float* c, const uint32_t* a, const uint32_t* b) {
    asm volatile(
        "mma.sync.aligned.m16n8k16.row.col.f32.bf16.bf16.f32 "
        "{%0,%1,%2,%3}, {%4,%5,%6,%7}, {%8,%9}, {%0,%1,%2,%3};"
        : "+f"(c[0]), "+f"(c[1]), "+f"(c[2]), "+f"(c[3])
        : "r"(a[0]), "r"(a[1]), "r"(a[2]), "r"(a[3]), "r"(b[0]), "r"(b[1]));
}

__global__ void __launch_bounds__(256, 2)
apred_mma_kernel(const float* __restrict__ z, float* __restrict__ out) {
    extern __shared__ __nv_bfloat16 sm[];
    __nv_bfloat16* Ahi = sm;
    __nv_bfloat16* Alo = sm + 128 * TPITCH;
    __nv_bfloat16* Bhi = sm + 2 * 128 * TPITCH;
    __nv_bfloat16* Blo = sm + 3 * 128 * TPITCH;

    int tid = threadIdx.x;
    int row0 = blockIdx.y * 128, col0 = blockIdx.x * 128;

    // ---- fill: split z rows into bf16 hi/lo ----
    for (int u = tid; u < 2048; u += 256) {
        int r = u >> 4, f4 = u & 15;
        int gr = row0 + r;
        float4 v = make_float4(0.f, 0.f, 0.f, 0.f);
        if (gr < N_NODES) v = *(const float4*)(z + (size_t)gr * 64 + f4 * 4);
        {
            __nv_bfloat16 h0 = __float2bfloat16_rn(v.x), h1 = __float2bfloat16_rn(v.y);
            __nv_bfloat16 h2 = __float2bfloat16_rn(v.z), h3 = __float2bfloat16_rn(v.w);
            __nv_bfloat16 l0 = __float2bfloat16_rn(v.x - __bfloat162float(h0));
            __nv_bfloat16 l1 = __float2bfloat16_rn(v.y - __bfloat162float(h1));
            __nv_bfloat16 l2 = __float2bfloat16_rn(v.z - __bfloat162float(h2));
            __nv_bfloat16 l3 = __float2bfloat16_rn(v.w - __bfloat162float(h3));
            int e = r * TPITCH + f4 * 4;
            *(uint32_t*)&Ahi[e]     = ((uint32_t)__bfloat16_as_ushort(h1) << 16) | __bfloat16_as_ushort(h0);
            *(uint32_t*)&Ahi[e + 2] = ((uint32_t)__bfloat16_as_ushort(h3) << 16) | __bfloat16_as_ushort(h2);
            *(uint32_t*)&Alo[e]     = ((uint32_t)__bfloat16_as_ushort(l1) << 16) | __bfloat16_as_ushort(l0);
            *(uint32_t*)&Alo[e + 2] = ((uint32_t)__bfloat16_as_ushort(l3) << 16) | __bfloat16_as_ushort(l2);
        }
        int gc = col0 + r;
        float4 w = make_float4(0.f, 0.f, 0.f, 0.f);
        if (gc < N_NODES) w = *(const float4*)(z + (size_t)gc * 64 + f4 * 4);
        {
            __nv_bfloat16 h0 = __float2bfloat16_rn(w.x), h1 = __float2bfloat16_rn(w.y);
            __nv_bfloat16 h2 = __float2bfloat16_rn(w.z), h3 = __float2bfloat16_rn(w.w);
            __nv_bfloat16 l0 = __float2bfloat16_rn(w.x - __bfloat162float(h0));
            __nv_bfloat16 l1 = __float2bfloat16_rn(w.y - __bfloat162float(h1));
            __nv_bfloat16 l2 = __float2bfloat16_rn(w.z - __bfloat162float(h2));
            __nv_bfloat16 l3 = __float2bfloat16_rn(w.w - __bfloat162float(h3));
            int e = r * TPITCH + f4 * 4;
            *(uint32_t*)&Bhi[e]     = ((uint32_t)__bfloat16_as_ushort(h1) << 16) | __bfloat16_as_ushort(h0);
            *(uint32_t*)&Bhi[e + 2] = ((uint32_t)__bfloat16_as_ushort(h3) << 16) | __bfloat16_as_ushort(h2);
            *(uint32_t*)&Blo[e]     = ((uint32_t)__bfloat16_as_ushort(l1) << 16) | __bfloat16_as_ushort(l0);
            *(uint32_t*)&Blo[e + 2] = ((uint32_t)__bfloat16_as_ushort(l3) << 16) | __bfloat16_as_ushort(l2);
        }
    }
    __syncthreads();

    int wid = tid >> 5, lane = tid & 31;
    int gid = lane >> 2, tig = lane & 3;
    int m0 = (wid & 3) * 32;
    int n0 = (wid >> 2) * 64;

    float acc[2][8][4];
#pragma unroll
    for (int h = 0; h < 2; h++)
#pragma unroll
        for (int nb = 0; nb < 8; nb++)
#pragma unroll
            for (int q = 0; q < 4; q++) acc[h][nb][q] = 0.f;

#pragma unroll
    for (int p = 0; p < 3; p++) {
        const __nv_bfloat16* Ap = (p == 2) ? Alo : Ahi;
        const __nv_bfloat16* Bp = (p == 1) ? Blo : Bhi;
#pragma unroll
        for (int ks = 0; ks < 4; ks++) {
            int k0 = ks * 16;
            uint32_t a[2][4];
#pragma unroll
            for (int h = 0; h < 2; h++) {
                int r = m0 + 16 * h + gid;
                int e = r * TPITCH + k0 + 2 * tig;
                a[h][0] = *(const uint32_t*)&Ap[e];
                a[h][1] = *(const uint32_t*)&Ap[e + 8 * TPITCH];
                a[h][2] = *(const uint32_t*)&Ap[e + 8];
                a[h][3] = *(const uint32_t*)&Ap[e + 8 * TPITCH + 8];
            }
#pragma unroll
            for (int nb = 0; nb < 8; nb++) {
                int nr = n0 + 8 * nb + gid;
                int e = nr * TPITCH + k0 + 2 * tig;
                uint32_t b[2];
                b[0] = *(const uint32_t*)&Bp[e];
                b[1] = *(const uint32_t*)&Bp[e + 8];
                mma_bf16(acc[0][nb], a[0], b);
                mma_bf16(acc[1][nb], a[1], b);
            }
        }
    }

    // ---- epilogue: sigmoid + guarded float2 stores (32B per quad) ----
#pragma unroll
    for (int h = 0; h < 2; h++) {
#pragma unroll
        for (int nb = 0; nb < 8; nb++) {
            float* q = acc[h][nb];
            int r0 = row0 + m0 + 16 * h + gid;
            int c  = col0 + n0 + 8 * nb + 2 * tig;
            if (c < N_NODES) {
                if (r0 < N_NODES) {
                    float2 v;
                    v.x = __fdividef(1.f, 1.f + __expf(-q[0]));
                    v.y = __fdividef(1.f, 1.f + __expf(-q[1]));
                    *(float2*)(out + (size_t)r0 * N_NODES + c) = v;
                }
                int r1 = r0 + 8;
                if (r1 < N_NODES) {
                    float2 v;
                    v.x = __fdividef(1.f, 1.f + __expf(-q[2]));
                    v.y = __fdividef(1.f, 1.f + __expf(-q[3]));
                    *(float2*)(out + (size_t)r1 * N_NODES + c) = v;
                }
            }
        }
    }
}

// ---------------- launch -----------------------------------------------------
extern "C" void kernel_launch(void* const* d_in, const int* in_sizes, int n_in,
                              void* d_out, int out_size) {
    const float* x     = (const float*)d_in[0];
    const int*   src   = (const int*)  d_in[1];
    const int*   dst   = (const int*)  d_in[2];
    const float* noise = (const float*)d_in[4];
    const float* W0  = (const float*)d_in[5];
    const float* b0  = (const float*)d_in[6];
    const float* g0  = (const float*)d_in[7];
    const float* be0 = (const float*)d_in[8];
    const float* Wm  = (const float*)d_in[9];
    const float* bm  = (const float*)d_in[10];
    const float* gm  = (const float*)d_in[11];
    const float* bem = (const float*)d_in[12];
    const float* Ws  = (const float*)d_in[13];
    const float* bs  = (const float*)d_in[14];
    const float* gs  = (const float*)d_in[15];
    const float* bes = (const float*)d_in[16];
    const float* Dw1 = (const float*)d_in[17];
    const float* Db1 = (const float*)d_in[18];
    const float* Dw2 = (const float*)d_in[19];
    const float* Db2 = (const float*)d_in[20];
    float* out = (float*)d_out;

    float* fsc; int* isc; double* sums;
    cudaGetSymbolAddress((void**)&fsc, g_fsc);
    cudaGetSymbolAddress((void**)&isc, g_isc);
    cudaGetSymbolAddress((void**)&sums, g_sums);

    float* HSA  = fsc + 0 * BUF;
    float* HSB  = fsc + 1 * BUF;
    float* SB1  = fsc + 2 * BUF;
    float* SB2  = fsc + 3 * BUF;
    float* SB3  = fsc + 4 * BUF;
    float* HID  = fsc + 5 * BUF;
    float* Z    = fsc + 8 * BUF;
    float* DIS  = fsc + 9 * BUF;
    float* H1   = fsc + 0 * BUF;   // HSA dead by decoder time
    int* CNT = isc;
    int* OFF = CNT + N_NODES;
    int* CUR = OFF + N_NODES + 16;   // padded so CUR is 16B-aligned for int4 stores
    int* CSR = CUR + N_NODES;

    // static streams/events (host objects only; created once)
    static cudaStream_t s1 = nullptr, s2 = nullptr;
    static cudaEvent_t evA = nullptr, evB = nullptr, evC = nullptr, evD = nullptr, evE = nullptr;
    if (!s1) {
        cudaStreamCreateWithFlags(&s1, cudaStreamNonBlocking);
        cudaStreamCreateWithFlags(&s2, cudaStreamNonBlocking);
        cudaEventCreateWithFlags(&evA, cudaEventDisableTiming);
        cudaEventCreateWithFlags(&evB, cudaEventDisableTiming);
        cudaEventCreateWithFlags(&evC, cudaEventDisableTiming);
        cudaEventCreateWithFlags(&evD, cudaEventDisableTiming);
        cudaEventCreateWithFlags(&evE, cudaEventDisableTiming);
    }

    const int APRED_SMEM = 4 * 128 * TPITCH * 2;   // 73728 bytes
    cudaFuncSetAttribute(apred_mma_kernel, cudaFuncAttributeMaxDynamicSharedMemorySize, APRED_SMEM);

    // fork at graph start: gemm1 (no deps — unscaled) on s1, prep chain on main
    cudaEventRecord(evA, 0);
    cudaStreamWaitEvent(s1, evA, 0);
    gemm_kernel<FIN_, DD, 3><<<750, 256, 0, s1>>>(x, W0, nullptr, HSA);
    cudaEventRecord(evB, s1);

    zero_all_kernel<<<47, 256>>>(CNT, sums);
    hist_kernel<<<1500, 256>>>(dst, CNT);
    scan_kernel<<<1, 1024>>>(CNT, OFF, CUR, DIS);
    fill_kernel<<<1500, 256>>>(src, dst, CUR, CSR);
    cudaStreamWaitEvent(0, evB, 0);                 // join: gather1 needs HSA + CSR

    // layer 1
    gather_sig_kernel<<<1500, 256>>>(HSA, DIS, OFF, CSR, b0, SB1);
    stats_kernel<<<64, 256>>>(SB1, sums);
    bn_apply_kernel<<<3000, 256>>>(SB1, sums, g0, be0, HID);

    // fork: mean branch on main, logstd branch on s2 (both end at stats)
    cudaEventRecord(evC, 0);
    cudaStreamWaitEvent(s2, evC, 0);

    gemm_kernel<DD, DD, 3><<<750, 256>>>(HID, Wm, nullptr, HSA);
    gather_sig_kernel<<<1500, 256>>>(HSA, DIS, OFF, CSR, bm, SB2);
    stats_kernel<<<64, 256>>>(SB2, sums + 128);

    gemm_kernel<DD, DD, 3><<<750, 256, 0, s2>>>(HID, Ws, nullptr, HSB);
    gather_sig_kernel<<<1500, 256, 0, s2>>>(HSB, DIS, OFF, CSR, bs, SB3);
    stats_kernel<<<64, 256, 0, s2>>>(SB3, sums + 256);
    cudaEventRecord(evD, s2);
    cudaStreamWaitEvent(0, evD, 0);                 // join before z

    // z = noise*exp(bn(SB3)) + bn(SB2)   (both BNs fused in)
    z_bn_kernel<<<3000, 256>>>(noise, SB2, SB3, sums, gm, bem, gs, bes, Z);

    // fork: decoder on s1 concurrent with apred on main (disjoint out regions)
    cudaEventRecord(evA, 0);
    cudaStreamWaitEvent(s1, evA, 0);
    gemm_kernel<DD, DD, 1><<<750, 256, 0, s1>>>(Z, Dw1, Db1, H1);
    gemm_kernel<DD, FIN_, 2><<<750, 256, 0, s1>>>(H1, Dw2, Db2, out);
    cudaEventRecord(evE, s1);

    dim3 grid((N_NODES + 127) / 128, (N_NODES + 127) / 128);
    apred_mma_kernel<<<grid, 256, APRED_SMEM>>>(Z, out + (size_t)N_NODES * FIN_);
    cudaStreamWaitEvent(0, evE, 0);                 // final join
}

// round 15
// speedup vs baseline: 1.0964x; 1.0654x over previous
#include <cuda_runtime.h>
#include <cuda_bf16.h>
#include <math.h>
#include <stdint.h>

#define N_NODES 12000
#define N_EDGES 384000
#define FIN_    128
#define DD      64
#define BUF     (N_NODES * DD)   // 768000

// Scratch (no allocation allowed)
__device__ float  g_fsc[9 * BUF + N_NODES];
// layout: CNT[12000] | OFF[12016 incl. pad => CUR 16B-aligned] | CUR[12000] | CSR[384000]
__device__ int    g_isc[N_NODES + (N_NODES + 16) + N_NODES + N_EDGES];
__device__ double g_sums[384];   // 3 layers x (64 sum + 64 sumsq)

// ---------------- graph prep ----------------
__global__ void zero_all_kernel(int* cnt, double* sums) {
    int i = blockIdx.x * 256 + threadIdx.x;
    if (i < N_NODES) cnt[i] = 0;
    if (i < 384) sums[i] = 0.0;
}

__global__ void hist_kernel(const int* __restrict__ dst, int* cnt) {
    int i = blockIdx.x * 256 + threadIdx.x;
    atomicAdd(&cnt[dst[i]], 1);
}

// shfl scan + vectorized int4/float4 memory (verified 22.6 -> 8.9us)
__global__ void scan_kernel(const int* __restrict__ cnt, int* __restrict__ off,
                            int* __restrict__ cur, float* __restrict__ dis) {
    __shared__ int wsum[32];
    const int C = 12;                        // 1000 threads * 12 = 12000 exact
    int tid = threadIdx.x;
    int lane = tid & 31, wid = tid >> 5;
    int base = tid * C;
    bool live = (tid < N_NODES / C);
    int loc[C];
    int s = 0;
    if (live) {
        const int4* c4 = (const int4*)(cnt + base);
        int4 a = c4[0], b = c4[1], c = c4[2];
        loc[0] = a.x; loc[1] = a.y; loc[2]  = a.z; loc[3]  = a.w;
        loc[4] = b.x; loc[5] = b.y; loc[6]  = b.z; loc[7]  = b.w;
        loc[8] = c.x; loc[9] = c.y; loc[10] = c.z; loc[11] = c.w;
#pragma unroll
        for (int j = 0; j < C; j++) s += loc[j];
    } else {
#pragma unroll
        for (int j = 0; j < C; j++) loc[j] = 0;
    }
    int ps = s;
#pragma unroll
    for (int d = 1; d < 32; d <<= 1) {
        int t = __shfl_up_sync(0xffffffff, ps, d);
        if (lane >= d) ps += t;
    }
    if (lane == 31) wsum[wid] = ps;
    __syncthreads();
    if (wid == 0) {
        int w = wsum[lane];
        int pw = w;
#pragma unroll
        for (int d = 1; d < 32; d <<= 1) {
            int t = __shfl_up_sync(0xffffffff, pw, d);
            if (lane >= d) pw += t;
        }
        wsum[lane] = pw - w;
    }
    __syncthreads();
    int run = wsum[wid] + ps - s;
    if (live) {
        int o[C];
        float dv[C];
#pragma unroll
        for (int j = 0; j < C; j++) {
            o[j] = run;
            dv[j] = rsqrtf((float)(loc[j] + 1));
            run += loc[j];
        }
        int4* o4 = (int4*)(off + base);
        int4* u4 = (int4*)(cur + base);
        float4* d4 = (float4*)(dis + base);
        o4[0] = make_int4(o[0], o[1], o[2],  o[3]);
        o4[1] = make_int4(o[4], o[5], o[6],  o[7]);
        o4[2] = make_int4(o[8], o[9], o[10], o[11]);
        u4[0] = make_int4(o[0], o[1], o[2],  o[3]);
        u4[1] = make_int4(o[4], o[5], o[6],  o[7]);
        u4[2] = make_int4(o[8], o[9], o[10], o[11]);
        d4[0] = make_float4(dv[0], dv[1], dv[2],  dv[3]);
        d4[1] = make_float4(dv[4], dv[5], dv[6],  dv[7]);
        d4[2] = make_float4(dv[8], dv[9], dv[10], dv[11]);
    }
    if (tid == 1023) off[N_NODES] = run;
}

__global__ void fill_kernel(const int* __restrict__ src, const int* __restrict__ dst,
                            int* cur, int* __restrict__ csr) {
    int i = blockIdx.x * 256 + threadIdx.x;
    int p = atomicAdd(&cur[dst[i]], 1);
    csr[p] = src[i];
}

// ---------------- small GEMM ----------------
// EPI 1: leaky_relu(v + aux[col]); EPI 2: v + aux[col]; EPI 3: plain v
template <int FIN, int NOUT, int EPI>
__global__ void gemm_kernel(const float* __restrict__ X, const float* __restrict__ W,
                            const float* __restrict__ aux, float* __restrict__ Y) {
    __shared__ float xs[16 * FIN];
    int tid = threadIdx.x;
    int rowbase = blockIdx.x * 16;
    const float4* Xg = (const float4*)(X + (size_t)rowbase * FIN);
    float4* xs4 = (float4*)xs;
#pragma unroll
    for (int u = tid; u < 16 * FIN / 4; u += 256) xs4[u] = Xg[u];
    __syncthreads();

    const int LANES = 256 / NOUT;
    const int RPT   = 16 / LANES;
    int col = tid % NOUT;
    int rl  = tid / NOUT;
    float acc[RPT];
#pragma unroll
    for (int r = 0; r < RPT; r++) acc[r] = 0.f;

#pragma unroll 4
    for (int k = 0; k < FIN; k++) {
        float w = __ldg(&W[k * NOUT + col]);
#pragma unroll
        for (int r = 0; r < RPT; r++)
            acc[r] += xs[(rl * RPT + r) * FIN + k] * w;
    }
#pragma unroll
    for (int r = 0; r < RPT; r++) {
        int row = rowbase + rl * RPT + r;
        float v = acc[r];
        if (EPI == 1 || EPI == 2) {
            v += aux[col];
            if (EPI == 1) v = (v > 0.f) ? v : 0.01f * v;
        }
        Y[(size_t)row * NOUT + col] = v;
    }
}

// ---- gather + bias + sigmoid: h unscaled; dis applied per-edge (4-unroll) --
__global__ void gather_sig_kernel(const float* __restrict__ hs, const float* __restrict__ dis,
                                  const int* __restrict__ off, const int* __restrict__ csr,
                                  const float* __restrict__ bias, float* __restrict__ sbuf) {
    int warp = (blockIdx.x * 256 + threadIdx.x) >> 5;
    int lane = threadIdx.x & 31;
    const float2* h2 = (const float2*)hs;
    float dd = dis[warp];
    float2 self = h2[(size_t)warp * 32 + lane];
    float2 acc = make_float2(dd * self.x, dd * self.y);
    int e0 = off[warp], e1 = off[warp + 1];
    int e = e0;
    for (; e + 4 <= e1; e += 4) {
        int s0 = __ldg(&csr[e]);
        int s1 = __ldg(&csr[e + 1]);
        int s2 = __ldg(&csr[e + 2]);
        int s3 = __ldg(&csr[e + 3]);
        float d0 = __ldg(&dis[s0]);
        float d1 = __ldg(&dis[s1]);
        float d2 = __ldg(&dis[s2]);
        float d3 = __ldg(&dis[s3]);
        float2 v0 = h2[(size_t)s0 * 32 + lane];
        float2 v1 = h2[(size_t)s1 * 32 + lane];
        float2 v2 = h2[(size_t)s2 * 32 + lane];
        float2 v3 = h2[(size_t)s3 * 32 + lane];
        acc.x += d0 * v0.x + d1 * v1.x + d2 * v2.x + d3 * v3.x;
        acc.y += d0 * v0.y + d1 * v1.y + d2 * v2.y + d3 * v3.y;
    }
    for (; e < e1; e++) {
        int s0 = __ldg(&csr[e]);
        float d0 = __ldg(&dis[s0]);
        float2 v0 = h2[(size_t)s0 * 32 + lane];
        acc.x += d0 * v0.x;
        acc.y += d0 * v0.y;
    }
    float2 bb = ((const float2*)bias)[lane];
    float vx = dd * acc.x + bb.x;
    float vy = dd * acc.y + bb.y;
    vx = __fdividef(1.f, 1.f + __expf(-vx));
    vy = __fdividef(1.f, 1.f + __expf(-vy));
    ((float2*)sbuf)[(size_t)warp * 32 + lane] = make_float2(vx, vy);
}

// ---------------- BatchNorm ----------------
__global__ void stats_kernel(const float* __restrict__ sbuf, double* __restrict__ sums) {
    int tid = threadIdx.x;
    int c = tid & 63, rg = tid >> 6;
    double s = 0.0, s2 = 0.0;
    for (int row = blockIdx.x * 4 + rg; row < N_NODES; row += 64 * 4) {
        float v = sbuf[(size_t)row * 64 + c];
        s += v; s2 += (double)v * (double)v;
    }
    __shared__ double sh[256], sh2[256];
    sh[tid] = s; sh2[tid] = s2;
    __syncthreads();
    if (rg == 0) {
        s  = sh[tid]  + sh[tid + 64]  + sh[tid + 128]  + sh[tid + 192];
        s2 = sh2[tid] + sh2[tid + 64] + sh2[tid + 128] + sh2[tid + 192];
        atomicAdd(&sums[c], s);
        atomicAdd(&sums[64 + c], s2);
    }
}

__global__ void bn_apply_kernel(const float* __restrict__ sbuf, const double* __restrict__ sums,
                                const float* __restrict__ gamma, const float* __restrict__ beta,
                                float* __restrict__ out) {
    int idx = blockIdx.x * 256 + threadIdx.x;
    int c = idx & 63;
    double mu  = sums[c] * (1.0 / N_NODES);
    double var = sums[64 + c] * (1.0 / N_NODES) - mu * mu;
    float inv = rsqrtf((float)var + 1e-4f);
    out[idx] = (float)((double)sbuf[idx] - mu) * inv * gamma[c] + beta[c];
}

// --- z = noise*exp(bn(SBs)) + bn(SBm); ALSO emit bf16 hi/lo split of z ------
__global__ void z_bn_kernel(const float* __restrict__ noise,
                            const float* __restrict__ SBm, const float* __restrict__ SBs,
                            const double* __restrict__ sums,
                            const float* __restrict__ gm, const float* __restrict__ bem,
                            const float* __restrict__ gs, const float* __restrict__ bes,
                            float* __restrict__ z,
                            __nv_bfloat16* __restrict__ zhi, __nv_bfloat16* __restrict__ zlo) {
    int idx = blockIdx.x * 256 + threadIdx.x;
    int c = idx & 63;
    const double INVN = 1.0 / N_NODES;
    double mum = sums[128 + c] * INVN;
    double varm = sums[128 + 64 + c] * INVN - mum * mum;
    float am = rsqrtf((float)varm + 1e-4f) * gm[c];
    float zm = (float)((double)SBm[idx] - mum) * am + bem[c];
    double mus = sums[256 + c] * INVN;
    double vars = sums[256 + 64 + c] * INVN - mus * mus;
    float as = rsqrtf((float)vars + 1e-4f) * gs[c];
    float zs = (float)((double)SBs[idx] - mus) * as + bes[c];
    float zv = noise[idx] * expf(zs) + zm;
    z[idx] = zv;
    __nv_bfloat16 h = __float2bfloat16_rn(zv);
    zhi[idx] = h;
    zlo[idx] = __float2bfloat16_rn(zv - __bfloat162float(h));
}

// ====== A_pred = sigmoid(z @ z^T) via mma.sync bf16 two-term split ==========
// Fill now copies precomputed zhi/zlo (uint4 copies, no conversion math).
// Mainloop/epilogue identical to the proven R4/R8 configuration.
#define TPITCH 72   // bf16 elements per smem row (144 bytes)

__device__ __forceinline__ void mma_bf16(float* c, const uint32_t* a, const uint32_t* b) {
    asm volatile(
        "mma.sync.aligned.m16n8k16.row.col.f32.bf16.bf16.f32 "
        "{%0,%1,%2,%3}, {%4,%5,%6,%7}, {%8,%9}, {%0,%1,%2,%3};"
        : "+f"(c[0]), "+f"(c[1]), "+f"(c[2]), "+f"(c[3])
        : "r"(a[0]), "r"(a[1]), "r"(a[2]), "r"(a[3]), "r"(b[0]), "r"(b[1]));
}

__global__ void __launch_bounds__(256, 2)
apred_mma_kernel(const __nv_bfloat16* __restrict__ zhi, const __nv_bfloat16* __restrict__ zlo,
                 float* __restrict__ out) {
    extern __shared__ __nv_bfloat16 sm[];
    __nv_bfloat16* Ahi = sm;
    __nv_bfloat16* Alo = sm + 128 * TPITCH;
    __nv_bfloat16* Bhi = sm + 2 * 128 * TPITCH;
    __nv_bfloat16* Blo = sm + 3 * 128 * TPITCH;

    int tid = threadIdx.x;
    int row0 = blockIdx.y * 128, col0 = blockIdx.x * 128;

    // ---- fill: uint4 copies from precomputed zhi/zlo (row = 8 uint4) ----
    {
        const uint4* zh4 = (const uint4*)zhi;
        const uint4* zl4 = (const uint4*)zlo;
        const uint4 Z4 = make_uint4(0u, 0u, 0u, 0u);
        for (int u = tid; u < 1024; u += 256) {
            int r = u >> 3, q = u & 7;                // q: which 16B chunk of row
            int boff = r * 144 + q * 16;              // 144B pitch, 16B aligned
            int gr = row0 + r;
            uint4 vh = Z4, vl = Z4;
            if (gr < N_NODES) { vh = zh4[gr * 8 + q]; vl = zl4[gr * 8 + q]; }
            *(uint4*)((char*)Ahi + boff) = vh;
            *(uint4*)((char*)Alo + boff) = vl;
            int gc = col0 + r;
            uint4 wh = Z4, wl = Z4;
            if (gc < N_NODES) { wh = zh4[gc * 8 + q]; wl = zl4[gc * 8 + q]; }
            *(uint4*)((char*)Bhi + boff) = wh;
            *(uint4*)((char*)Blo + boff) = wl;
        }
    }
    __syncthreads();

    int wid = tid >> 5, lane = tid & 31;
    int gid = lane >> 2, tig = lane & 3;
    int m0 = (wid & 3) * 32;
    int n0 = (wid >> 2) * 64;

    float acc[2][8][4];
#pragma unroll
    for (int h = 0; h < 2; h++)
#pragma unroll
        for (int nb = 0; nb < 8; nb++)
#pragma unroll
            for (int q = 0; q < 4; q++) acc[h][nb][q] = 0.f;

#pragma unroll
    for (int p = 0; p < 3; p++) {
        const __nv_bfloat16* Ap = (p == 2) ? Alo : Ahi;
        const __nv_bfloat16* Bp = (p == 1) ? Blo : Bhi;
#pragma unroll
        for (int ks = 0; ks < 4; ks++) {
            int k0 = ks * 16;
            uint32_t a[2][4];
#pragma unroll
            for (int h = 0; h < 2; h++) {
                int r = m0 + 16 * h + gid;
                int e = r * TPITCH + k0 + 2 * tig;
                a[h][0] = *(const uint32_t*)&Ap[e];
                a[h][1] = *(const uint32_t*)&Ap[e + 8 * TPITCH];
                a[h][2] = *(const uint32_t*)&Ap[e + 8];
                a[h][3] = *(const uint32_t*)&Ap[e + 8 * TPITCH + 8];
            }
#pragma unroll
            for (int nb = 0; nb < 8; nb++) {
                int nr = n0 + 8 * nb + gid;
                int e = nr * TPITCH + k0 + 2 * tig;
                uint32_t b[2];
                b[0] = *(const uint32_t*)&Bp[e];
                b[1] = *(const uint32_t*)&Bp[e + 8];
                mma_bf16(acc[0][nb], a[0], b);
                mma_bf16(acc[1][nb], a[1], b);
            }
        }
    }

    // ---- epilogue: sigmoid + guarded float2 stores (32B per quad) ----
#pragma unroll
    for (int h = 0; h < 2; h++) {
#pragma unroll
        for (int nb = 0; nb < 8; nb++) {
            float* q = acc[h][nb];
            int r0 = row0 + m0 + 16 * h + gid;
            int c  = col0 + n0 + 8 * nb + 2 * tig;
            if (c < N_NODES) {
                if (r0 < N_NODES) {
                    float2 v;
                    v.x = __fdividef(1.f, 1.f + __expf(-q[0]));
                    v.y = __fdividef(1.f, 1.f + __expf(-q[1]));
                    *(float2*)(out + (size_t)r0 * N_NODES + c) = v;
                }
                int r1 = r0 + 8;
                if (r1 < N_NODES) {
                    float2 v;
                    v.x = __fdividef(1.f, 1.f + __expf(-q[2]));
                    v.y = __fdividef(1.f, 1.f + __expf(-q[3]));
                    *(float2*)(out + (size_t)r1 * N_NODES + c) = v;
                }
            }
        }
    }
}

// ---------------- launch -----------------------------------------------------
extern "C" void kernel_launch(void* const* d_in, const int* in_sizes, int n_in,
                              void* d_out, int out_size) {
    const float* x     = (const float*)d_in[0];
    const int*   src   = (const int*)  d_in[1];
    const int*   dst   = (const int*)  d_in[2];
    const float* noise = (const float*)d_in[4];
    const float* W0  = (const float*)d_in[5];
    const float* b0  = (const float*)d_in[6];
    const float* g0  = (const float*)d_in[7];
    const float* be0 = (const float*)d_in[8];
    const float* Wm  = (const float*)d_in[9];
    const float* bm  = (const float*)d_in[10];
    const float* gm  = (const float*)d_in[11];
    const float* bem = (const float*)d_in[12];
    const float* Ws  = (const float*)d_in[13];
    const float* bs  = (const float*)d_in[14];
    const float* gs  = (const float*)d_in[15];
    const float* bes = (const float*)d_in[16];
    const float* Dw1 = (const float*)d_in[17];
    const float* Db1 = (const float*)d_in[18];
    const float* Dw2 = (const float*)d_in[19];
    const float* Db2 = (const float*)d_in[20];
    float* out = (float*)d_out;

    float* fsc; int* isc; double* sums;
    cudaGetSymbolAddress((void**)&fsc, g_fsc);
    cudaGetSymbolAddress((void**)&isc, g_isc);
    cudaGetSymbolAddress((void**)&sums, g_sums);

    float* HSA  = fsc + 0 * BUF;
    float* HSB  = fsc + 1 * BUF;
    float* SB1  = fsc + 2 * BUF;
    float* SB2  = fsc + 3 * BUF;
    float* SB3  = fsc + 4 * BUF;
    float* HID  = fsc + 5 * BUF;
    __nv_bfloat16* ZHI = (__nv_bfloat16*)(fsc + 6 * BUF);   // 768000 bf16 = 1.5MB
    __nv_bfloat16* ZLO = (__nv_bfloat16*)(fsc + 7 * BUF);
    float* Z    = fsc + 8 * BUF;
    float* DIS  = fsc + 9 * BUF;
    float* H1   = fsc + 0 * BUF;   // HSA dead by decoder time
    int* CNT = isc;
    int* OFF = CNT + N_NODES;
    int* CUR = OFF + N_NODES + 16;   // padded so CUR is 16B-aligned
    int* CSR = CUR + N_NODES;

    // static streams/events (host objects only; created once)
    static cudaStream_t s1 = nullptr, s2 = nullptr;
    static cudaEvent_t evA = nullptr, evB = nullptr, evC = nullptr, evD = nullptr, evE = nullptr;
    if (!s1) {
        cudaStreamCreateWithFlags(&s1, cudaStreamNonBlocking);
        cudaStreamCreateWithFlags(&s2, cudaStreamNonBlocking);
        cudaEventCreateWithFlags(&evA, cudaEventDisableTiming);
        cudaEventCreateWithFlags(&evB, cudaEventDisableTiming);
        cudaEventCreateWithFlags(&evC, cudaEventDisableTiming);
        cudaEventCreateWithFlags(&evD, cudaEventDisableTiming);
        cudaEventCreateWithFlags(&evE, cudaEventDisableTiming);
    }

    const int APRED_SMEM = 4 * 128 * TPITCH * 2;   // 73728 bytes
    cudaFuncSetAttribute(apred_mma_kernel, cudaFuncAttributeMaxDynamicSharedMemorySize, APRED_SMEM);

    // fork at graph start: gemm1 (no deps — unscaled) on s1, prep chain on main
    cudaEventRecord(evA, 0);
    cudaStreamWaitEvent(s1, evA, 0);
    gemm_kernel<FIN_, DD, 3><<<750, 256, 0, s1>>>(x, W0, nullptr, HSA);
    cudaEventRecord(evB, s1);

    zero_all_kernel<<<47, 256>>>(CNT, sums);
    hist_kernel<<<1500, 256>>>(dst, CNT);
    scan_kernel<<<1, 1024>>>(CNT, OFF, CUR, DIS);
    fill_kernel<<<1500, 256>>>(src, dst, CUR, CSR);
    cudaStreamWaitEvent(0, evB, 0);                 // join: gather1 needs HSA + CSR

    // layer 1
    gather_sig_kernel<<<1500, 256>>>(HSA, DIS, OFF, CSR, b0, SB1);
    stats_kernel<<<64, 256>>>(SB1, sums);
    bn_apply_kernel<<<3000, 256>>>(SB1, sums, g0, be0, HID);

    // fork: mean branch on main, logstd branch on s2 (both end at stats)
    cudaEventRecord(evC, 0);
    cudaStreamWaitEvent(s2, evC, 0);

    gemm_kernel<DD, DD, 3><<<750, 256>>>(HID, Wm, nullptr, HSA);
    gather_sig_kernel<<<1500, 256>>>(HSA, DIS, OFF, CSR, bm, SB2);
    stats_kernel<<<64, 256>>>(SB2, sums + 128);

    gemm_kernel<DD, DD, 3><<<750, 256, 0, s2>>>(HID, Ws, nullptr, HSB);
    gather_sig_kernel<<<1500, 256, 0, s2>>>(HSB, DIS, OFF, CSR, bs, SB3);
    stats_kernel<<<64, 256, 0, s2>>>(SB3, sums + 256);
    cudaEventRecord(evD, s2);
    cudaStreamWaitEvent(0, evD, 0);                 // join before z

    // z = noise*exp(bn(SB3)) + bn(SB2); also emits bf16 hi/lo split
    z_bn_kernel<<<3000, 256>>>(noise, SB2, SB3, sums, gm, bem, gs, bes, Z, ZHI, ZLO);

    // fork: decoder on s1 concurrent with apred on main (disjoint out regions)
    cudaEventRecord(evA, 0);
    cudaStreamWaitEvent(s1, evA, 0);
    gemm_kernel<DD, DD, 1><<<750, 256, 0, s1>>>(Z, Dw1, Db1, H1);
    gemm_kernel<DD, FIN_, 2><<<750, 256, 0, s1>>>(H1, Dw2, Db2, out);
    cudaEventRecord(evE, s1);

    dim3 grid((N_NODES + 127) / 128, (N_NODES + 127) / 128);
    apred_mma_kernel<<<grid, 256, APRED_SMEM>>>(ZHI, ZLO, out + (size_t)N_NODES * FIN_);
    cudaStreamWaitEvent(0, evE, 0);                 // final join
}

// round 16
// speedup vs baseline: 1.1180x; 1.0197x over previous
#include <cuda_runtime.h>
#include <cuda_bf16.h>
#include <math.h>
#include <stdint.h>

#define N_NODES 12000
#define N_EDGES 384000
#define FIN_    128
#define DD      64
#define BUF     (N_NODES * DD)   // 768000

// Scratch (no allocation allowed)
__device__ float  g_fsc[9 * BUF + N_NODES];
// layout: CNT[12000] | OFF[12016 incl. pad => CUR 16B-aligned] | CUR[12000] | CSR[384000]
__device__ int    g_isc[N_NODES + (N_NODES + 16) + N_NODES + N_EDGES];
__device__ double g_sums[384];   // 3 layers x (64 sum + 64 sumsq)

// ---------------- graph prep ----------------
__global__ void zero_all_kernel(int* cnt, double* sums) {
    int i = blockIdx.x * 256 + threadIdx.x;
    if (i < N_NODES) cnt[i] = 0;
    if (i < 384) sums[i] = 0.0;
}

__global__ void hist_kernel(const int* __restrict__ dst, int* cnt) {
    int i = blockIdx.x * 256 + threadIdx.x;
    atomicAdd(&cnt[dst[i]], 1);
}

// shfl scan + vectorized int4/float4 memory (verified 22.6 -> 8.9us)
__global__ void scan_kernel(const int* __restrict__ cnt, int* __restrict__ off,
                            int* __restrict__ cur, float* __restrict__ dis) {
    __shared__ int wsum[32];
    const int C = 12;                        // 1000 threads * 12 = 12000 exact
    int tid = threadIdx.x;
    int lane = tid & 31, wid = tid >> 5;
    int base = tid * C;
    bool live = (tid < N_NODES / C);
    int loc[C];
    int s = 0;
    if (live) {
        const int4* c4 = (const int4*)(cnt + base);
        int4 a = c4[0], b = c4[1], c = c4[2];
        loc[0] = a.x; loc[1] = a.y; loc[2]  = a.z; loc[3]  = a.w;
        loc[4] = b.x; loc[5] = b.y; loc[6]  = b.z; loc[7]  = b.w;
        loc[8] = c.x; loc[9] = c.y; loc[10] = c.z; loc[11] = c.w;
#pragma unroll
        for (int j = 0; j < C; j++) s += loc[j];
    } else {
#pragma unroll
        for (int j = 0; j < C; j++) loc[j] = 0;
    }
    int ps = s;
#pragma unroll
    for (int d = 1; d < 32; d <<= 1) {
        int t = __shfl_up_sync(0xffffffff, ps, d);
        if (lane >= d) ps += t;
    }
    if (lane == 31) wsum[wid] = ps;
    __syncthreads();
    if (wid == 0) {
        int w = wsum[lane];
        int pw = w;
#pragma unroll
        for (int d = 1; d < 32; d <<= 1) {
            int t = __shfl_up_sync(0xffffffff, pw, d);
            if (lane >= d) pw += t;
        }
        wsum[lane] = pw - w;
    }
    __syncthreads();
    int run = wsum[wid] + ps - s;
    if (live) {
        int o[C];
        float dv[C];
#pragma unroll
        for (int j = 0; j < C; j++) {
            o[j] = run;
            dv[j] = rsqrtf((float)(loc[j] + 1));
            run += loc[j];
        }
        int4* o4 = (int4*)(off + base);
        int4* u4 = (int4*)(cur + base);
        float4* d4 = (float4*)(dis + base);
        o4[0] = make_int4(o[0], o[1], o[2],  o[3]);
        o4[1] = make_int4(o[4], o[5], o[6],  o[7]);
        o4[2] = make_int4(o[8], o[9], o[10], o[11]);
        u4[0] = make_int4(o[0], o[1], o[2],  o[3]);
        u4[1] = make_int4(o[4], o[5], o[6],  o[7]);
        u4[2] = make_int4(o[8], o[9], o[10], o[11]);
        d4[0] = make_float4(dv[0], dv[1], dv[2],  dv[3]);
        d4[1] = make_float4(dv[4], dv[5], dv[6],  dv[7]);
        d4[2] = make_float4(dv[8], dv[9], dv[10], dv[11]);
    }
    if (tid == 1023) off[N_NODES] = run;
}

__global__ void fill_kernel(const int* __restrict__ src, const int* __restrict__ dst,
                            int* cur, int* __restrict__ csr) {
    int i = blockIdx.x * 256 + threadIdx.x;
    int p = atomicAdd(&cur[dst[i]], 1);
    csr[p] = src[i];
}

// ---------------- small GEMM ----------------
// EPI 1: leaky_relu(v + aux[col]); EPI 2: v + aux[col]; EPI 3: plain v
template <int FIN, int NOUT, int EPI>
__global__ void gemm_kernel(const float* __restrict__ X, const float* __restrict__ W,
                            const float* __restrict__ aux, float* __restrict__ Y) {
    __shared__ float xs[16 * FIN];
    int tid = threadIdx.x;
    int rowbase = blockIdx.x * 16;
    const float4* Xg = (const float4*)(X + (size_t)rowbase * FIN);
    float4* xs4 = (float4*)xs;
#pragma unroll
    for (int u = tid; u < 16 * FIN / 4; u += 256) xs4[u] = Xg[u];
    __syncthreads();

    const int LANES = 256 / NOUT;
    const int RPT   = 16 / LANES;
    int col = tid % NOUT;
    int rl  = tid / NOUT;
    float acc[RPT];
#pragma unroll
    for (int r = 0; r < RPT; r++) acc[r] = 0.f;

#pragma unroll 4
    for (int k = 0; k < FIN; k++) {
        float w = __ldg(&W[k * NOUT + col]);
#pragma unroll
        for (int r = 0; r < RPT; r++)
            acc[r] += xs[(rl * RPT + r) * FIN + k] * w;
    }
#pragma unroll
    for (int r = 0; r < RPT; r++) {
        int row = rowbase + rl * RPT + r;
        float v = acc[r];
        if (EPI == 1 || EPI == 2) {
            v += aux[col];
            if (EPI == 1) v = (v > 0.f) ? v : 0.01f * v;
        }
        Y[(size_t)row * NOUT + col] = v;
    }
}

// ---- branch GEMM with BN1 folded in: Y = bn(S)@W = (S.*a)@W + sum_k d[k]W[k,:]
// a = inv*gamma, d = beta - mu*a, derived per block from f64 sums. 64x64 only.
__global__ void gemm_bnfold_kernel(const float* __restrict__ S, const float* __restrict__ W,
                                   const double* __restrict__ sums,
                                   const float* __restrict__ gamma, const float* __restrict__ beta,
                                   float* __restrict__ Y) {
    __shared__ float xs[16 * 64];
    __shared__ float afold[64], dfold[64];
    int tid = threadIdx.x;
    int rowbase = blockIdx.x * 16;
    if (tid < 64) {
        double mu  = sums[tid] * (1.0 / N_NODES);
        double var = sums[64 + tid] * (1.0 / N_NODES) - mu * mu;
        float a = rsqrtf((float)var + 1e-4f) * gamma[tid];
        afold[tid] = a;
        dfold[tid] = beta[tid] - (float)mu * a;
    }
    __syncthreads();
    const float4* Sg = (const float4*)(S + (size_t)rowbase * 64);
    float4* xs4 = (float4*)xs;
    {
        float4 v = Sg[tid];                 // 256 threads = 16*64/4 exact
        int k = (tid & 15) * 4;
        v.x *= afold[k]; v.y *= afold[k + 1]; v.z *= afold[k + 2]; v.w *= afold[k + 3];
        xs4[tid] = v;
    }
    __syncthreads();

    int col = tid & 63;
    int rl  = tid >> 6;                     // 4 rows per thread
    float acc[4] = {0.f, 0.f, 0.f, 0.f};
    float bacc = 0.f;
#pragma unroll 4
    for (int k = 0; k < 64; k++) {
        float w = __ldg(&W[k * 64 + col]);
#pragma unroll
        for (int r = 0; r < 4; r++)
            acc[r] += xs[(rl * 4 + r) * 64 + k] * w;
        bacc += dfold[k] * w;
    }
#pragma unroll
    for (int r = 0; r < 4; r++) {
        int row = rowbase + rl * 4 + r;
        Y[(size_t)row * 64 + col] = acc[r] + bacc;
    }
}

// ---- gather + bias + sigmoid: h unscaled; dis applied per-edge (4-unroll) --
__global__ void gather_sig_kernel(const float* __restrict__ hs, const float* __restrict__ dis,
                                  const int* __restrict__ off, const int* __restrict__ csr,
                                  const float* __restrict__ bias, float* __restrict__ sbuf) {
    int warp = (blockIdx.x * 256 + threadIdx.x) >> 5;
    int lane = threadIdx.x & 31;
    const float2* h2 = (const float2*)hs;
    float dd = dis[warp];
    float2 self = h2[(size_t)warp * 32 + lane];
    float2 acc = make_float2(dd * self.x, dd * self.y);
    int e0 = off[warp], e1 = off[warp + 1];
    int e = e0;
    for (; e + 4 <= e1; e += 4) {
        int s0 = __ldg(&csr[e]);
        int s1 = __ldg(&csr[e + 1]);
        int s2 = __ldg(&csr[e + 2]);
        int s3 = __ldg(&csr[e + 3]);
        float d0 = __ldg(&dis[s0]);
        float d1 = __ldg(&dis[s1]);
        float d2 = __ldg(&dis[s2]);
        float d3 = __ldg(&dis[s3]);
        float2 v0 = h2[(size_t)s0 * 32 + lane];
        float2 v1 = h2[(size_t)s1 * 32 + lane];
        float2 v2 = h2[(size_t)s2 * 32 + lane];
        float2 v3 = h2[(size_t)s3 * 32 + lane];
        acc.x += d0 * v0.x + d1 * v1.x + d2 * v2.x + d3 * v3.x;
        acc.y += d0 * v0.y + d1 * v1.y + d2 * v2.y + d3 * v3.y;
    }
    for (; e < e1; e++) {
        int s0 = __ldg(&csr[e]);
        float d0 = __ldg(&dis[s0]);
        float2 v0 = h2[(size_t)s0 * 32 + lane];
        acc.x += d0 * v0.x;
        acc.y += d0 * v0.y;
    }
    float2 bb = ((const float2*)bias)[lane];
    float vx = dd * acc.x + bb.x;
    float vy = dd * acc.y + bb.y;
    vx = __fdividef(1.f, 1.f + __expf(-vx));
    vy = __fdividef(1.f, 1.f + __expf(-vy));
    ((float2*)sbuf)[(size_t)warp * 32 + lane] = make_float2(vx, vy);
}

// ---------------- BatchNorm ----------------
__global__ void stats_kernel(const float* __restrict__ sbuf, double* __restrict__ sums) {
    int tid = threadIdx.x;
    int c = tid & 63, rg = tid >> 6;
    double s = 0.0, s2 = 0.0;
    for (int row = blockIdx.x * 4 + rg; row < N_NODES; row += 64 * 4) {
        float v = sbuf[(size_t)row * 64 + c];
        s += v; s2 += (double)v * (double)v;
    }
    __shared__ double sh[256], sh2[256];
    sh[tid] = s; sh2[tid] = s2;
    __syncthreads();
    if (rg == 0) {
        s  = sh[tid]  + sh[tid + 64]  + sh[tid + 128]  + sh[tid + 192];
        s2 = sh2[tid] + sh2[tid + 64] + sh2[tid + 128] + sh2[tid + 192];
        atomicAdd(&sums[c], s);
        atomicAdd(&sums[64 + c], s2);
    }
}

// --- z = noise*exp(bn(SBs)) + bn(SBm); ALSO emit bf16 hi/lo split of z ------
__global__ void z_bn_kernel(const float* __restrict__ noise,
                            const float* __restrict__ SBm, const float* __restrict__ SBs,
                            const double* __restrict__ sums,
                            const float* __restrict__ gm, const float* __restrict__ bem,
                            const float* __restrict__ gs, const float* __restrict__ bes,
                            float* __restrict__ z,
                            __nv_bfloat16* __restrict__ zhi, __nv_bfloat16* __restrict__ zlo) {
    int idx = blockIdx.x * 256 + threadIdx.x;
    int c = idx & 63;
    const double INVN = 1.0 / N_NODES;
    double mum = sums[128 + c] * INVN;
    double varm = sums[128 + 64 + c] * INVN - mum * mum;
    float am = rsqrtf((float)varm + 1e-4f) * gm[c];
    float zm = (float)((double)SBm[idx] - mum) * am + bem[c];
    double mus = sums[256 + c] * INVN;
    double vars = sums[256 + 64 + c] * INVN - mus * mus;
    float as = rsqrtf((float)vars + 1e-4f) * gs[c];
    float zs = (float)((double)SBs[idx] - mus) * as + bes[c];
    float zv = noise[idx] * expf(zs) + zm;
    z[idx] = zv;
    __nv_bfloat16 h = __float2bfloat16_rn(zv);
    zhi[idx] = h;
    zlo[idx] = __float2bfloat16_rn(zv - __bfloat162float(h));
}

// ====== A_pred = sigmoid(z @ z^T) via mma.sync bf16 two-term split ==========
// Fill copies precomputed zhi/zlo (uint4, no conversion math). Mainloop and
// epilogue identical to the proven configuration.
#define TPITCH 72   // bf16 elements per smem row (144 bytes)

__device__ __forceinline__ void mma_bf16(float* c, const uint32_t* a, const uint32_t* b) {
    asm volatile(
        "mma.sync.aligned.m16n8k16.row.col.f32.bf16.bf16.f32 "
        "{%0,%1,%2,%3}, {%4,%5,%6,%7}, {%8,%9}, {%0,%1,%2,%3};"
        : "+f"(c[0]), "+f"(c[1]), "+f"(c[2]), "+f"(c[3])
        : "r"(a[0]), "r"(a[1]), "r"(a[2]), "r"(a[3]), "r"(b[0]), "r"(b[1]));
}

__global__ void __launch_bounds__(256, 2)
apred_mma_kernel(const __nv_bfloat16* __restrict__ zhi, const __nv_bfloat16* __restrict__ zlo,
                 float* __restrict__ out) {
    extern __shared__ __nv_bfloat16 sm[];
    __nv_bfloat16* Ahi = sm;
    __nv_bfloat16* Alo = sm + 128 * TPITCH;
    __nv_bfloat16* Bhi = sm + 2 * 128 * TPITCH;
    __nv_bfloat16* Blo = sm + 3 * 128 * TPITCH;

    int tid = threadIdx.x;
    int row0 = blockIdx.y * 128, col0 = blockIdx.x * 128;

    // ---- fill: uint4 copies from precomputed zhi/zlo (row = 8 uint4) ----
    {
        const uint4* zh4 = (const uint4*)zhi;
        const uint4* zl4 = (const uint4*)zlo;
        const uint4 Z4 = make_uint4(0u, 0u, 0u, 0u);
        for (int u = tid; u < 1024; u += 256) {
            int r = u >> 3, q = u & 7;
            int boff = r * 144 + q * 16;
            int gr = row0 + r;
            uint4 vh = Z4, vl = Z4;
            if (gr < N_NODES) { vh = zh4[gr * 8 + q]; vl = zl4[gr * 8 + q]; }
            *(uint4*)((char*)Ahi + boff) = vh;
            *(uint4*)((char*)Alo + boff) = vl;
            int gc = col0 + r;
            uint4 wh = Z4, wl = Z4;
            if (gc < N_NODES) { wh = zh4[gc * 8 + q]; wl = zl4[gc * 8 + q]; }
            *(uint4*)((char*)Bhi + boff) = wh;
            *(uint4*)((char*)Blo + boff) = wl;
        }
    }
    __syncthreads();

    int wid = tid >> 5, lane = tid & 31;
    int gid = lane >> 2, tig = lane & 3;
    int m0 = (wid & 3) * 32;
    int n0 = (wid >> 2) * 64;

    float acc[2][8][4];
#pragma unroll
    for (int h = 0; h < 2; h++)
#pragma unroll
        for (int nb = 0; nb < 8; nb++)
#pragma unroll
            for (int q = 0; q < 4; q++) acc[h][nb][q] = 0.f;

#pragma unroll
    for (int p = 0; p < 3; p++) {
        const __nv_bfloat16* Ap = (p == 2) ? Alo : Ahi;
        const __nv_bfloat16* Bp = (p == 1) ? Blo : Bhi;
#pragma unroll
        for (int ks = 0; ks < 4; ks++) {
            int k0 = ks * 16;
            uint32_t a[2][4];
#pragma unroll
            for (int h = 0; h < 2; h++) {
                int r = m0 + 16 * h + gid;
                int e = r * TPITCH + k0 + 2 * tig;
                a[h][0] = *(const uint32_t*)&Ap[e];
                a[h][1] = *(const uint32_t*)&Ap[e + 8 * TPITCH];
                a[h][2] = *(const uint32_t*)&Ap[e + 8];
                a[h][3] = *(const uint32_t*)&Ap[e + 8 * TPITCH + 8];
            }
#pragma unroll
            for (int nb = 0; nb < 8; nb++) {
                int nr = n0 + 8 * nb + gid;
                int e = nr * TPITCH + k0 + 2 * tig;
                uint32_t b[2];
                b[0] = *(const uint32_t*)&Bp[e];
                b[1] = *(const uint32_t*)&Bp[e + 8];
                mma_bf16(acc[0][nb], a[0], b);
                mma_bf16(acc[1][nb], a[1], b);
            }
        }
    }

    // ---- epilogue: sigmoid + guarded float2 stores (32B per quad) ----
#pragma unroll
    for (int h = 0; h < 2; h++) {
#pragma unroll
        for (int nb = 0; nb < 8; nb++) {
            float* q = acc[h][nb];
            int r0 = row0 + m0 + 16 * h + gid;
            int c  = col0 + n0 + 8 * nb + 2 * tig;
            if (c < N_NODES) {
                if (r0 < N_NODES) {
                    float2 v;
                    v.x = __fdividef(1.f, 1.f + __expf(-q[0]));
                    v.y = __fdividef(1.f, 1.f + __expf(-q[1]));
                    *(float2*)(out + (size_t)r0 * N_NODES + c) = v;
                }
                int r1 = r0 + 8;
                if (r1 < N_NODES) {
                    float2 v;
                    v.x = __fdividef(1.f, 1.f + __expf(-q[2]));
                    v.y = __fdividef(1.f, 1.f + __expf(-q[3]));
                    *(float2*)(out + (size_t)r1 * N_NODES + c) = v;
                }
            }
        }
    }
}

// ---------------- launch -----------------------------------------------------
extern "C" void kernel_launch(void* const* d_in, const int* in_sizes, int n_in,
                              void* d_out, int out_size) {
    const float* x     = (const float*)d_in[0];
    const int*   src   = (const int*)  d_in[1];
    const int*   dst   = (const int*)  d_in[2];
    const float* noise = (const float*)d_in[4];
    const float* W0  = (const float*)d_in[5];
    const float* b0  = (const float*)d_in[6];
    const float* g0  = (const float*)d_in[7];
    const float* be0 = (const float*)d_in[8];
    const float* Wm  = (const float*)d_in[9];
    const float* bm  = (const float*)d_in[10];
    const float* gm  = (const float*)d_in[11];
    const float* bem = (const float*)d_in[12];
    const float* Ws  = (const float*)d_in[13];
    const float* bs  = (const float*)d_in[14];
    const float* gs  = (const float*)d_in[15];
    const float* bes = (const float*)d_in[16];
    const float* Dw1 = (const float*)d_in[17];
    const float* Db1 = (const float*)d_in[18];
    const float* Dw2 = (const float*)d_in[19];
    const float* Db2 = (const float*)d_in[20];
    float* out = (float*)d_out;

    float* fsc; int* isc; double* sums;
    cudaGetSymbolAddress((void**)&fsc, g_fsc);
    cudaGetSymbolAddress((void**)&isc, g_isc);
    cudaGetSymbolAddress((void**)&sums, g_sums);

    float* HSA  = fsc + 0 * BUF;
    float* HSB  = fsc + 1 * BUF;
    float* SB1  = fsc + 2 * BUF;
    float* SB2  = fsc + 3 * BUF;
    float* SB3  = fsc + 4 * BUF;
    __nv_bfloat16* ZHI = (__nv_bfloat16*)(fsc + 6 * BUF);   // 768000 bf16 = 1.5MB
    __nv_bfloat16* ZLO = (__nv_bfloat16*)(fsc + 7 * BUF);
    float* Z    = fsc + 8 * BUF;
    float* DIS  = fsc + 9 * BUF;
    float* H1   = fsc + 0 * BUF;   // HSA dead by decoder time
    int* CNT = isc;
    int* OFF = CNT + N_NODES;
    int* CUR = OFF + N_NODES + 16;   // padded so CUR is 16B-aligned
    int* CSR = CUR + N_NODES;

    // static streams/events (host objects only; created once)
    static cudaStream_t s1 = nullptr, s2 = nullptr;
    static cudaEvent_t evA = nullptr, evB = nullptr, evC = nullptr, evD = nullptr, evE = nullptr;
    if (!s1) {
        cudaStreamCreateWithFlags(&s1, cudaStreamNonBlocking);
        cudaStreamCreateWithFlags(&s2, cudaStreamNonBlocking);
        cudaEventCreateWithFlags(&evA, cudaEventDisableTiming);
        cudaEventCreateWithFlags(&evB, cudaEventDisableTiming);
        cudaEventCreateWithFlags(&evC, cudaEventDisableTiming);
        cudaEventCreateWithFlags(&evD, cudaEventDisableTiming);
        cudaEventCreateWithFlags(&evE, cudaEventDisableTiming);
    }

    const int APRED_SMEM = 4 * 128 * TPITCH * 2;   // 73728 bytes
    cudaFuncSetAttribute(apred_mma_kernel, cudaFuncAttributeMaxDynamicSharedMemorySize, APRED_SMEM);

    // fork at graph start: gemm1 (no deps — unscaled) on s1, prep chain on main
    cudaEventRecord(evA, 0);
    cudaStreamWaitEvent(s1, evA, 0);
    gemm_kernel<FIN_, DD, 3><<<750, 256, 0, s1>>>(x, W0, nullptr, HSA);
    cudaEventRecord(evB, s1);

    zero_all_kernel<<<47, 256>>>(CNT, sums);
    hist_kernel<<<1500, 256>>>(dst, CNT);
    scan_kernel<<<1, 1024>>>(CNT, OFF, CUR, DIS);
    fill_kernel<<<1500, 256>>>(src, dst, CUR, CSR);
    cudaStreamWaitEvent(0, evB, 0);                 // join: gather1 needs HSA + CSR

    // layer 1 (no bn_apply: BN1 folded into the branch gemms)
    gather_sig_kernel<<<1500, 256>>>(HSA, DIS, OFF, CSR, b0, SB1);
    stats_kernel<<<64, 256>>>(SB1, sums);

    // fork: mean branch on main, logstd branch on s2 (both end at stats)
    cudaEventRecord(evC, 0);
    cudaStreamWaitEvent(s2, evC, 0);

    gemm_bnfold_kernel<<<750, 256>>>(SB1, Wm, sums, g0, be0, HSA);
    gather_sig_kernel<<<1500, 256>>>(HSA, DIS, OFF, CSR, bm, SB2);
    stats_kernel<<<64, 256>>>(SB2, sums + 128);

    gemm_bnfold_kernel<<<750, 256, 0, s2>>>(SB1, Ws, sums, g0, be0, HSB);
    gather_sig_kernel<<<1500, 256, 0, s2>>>(HSB, DIS, OFF, CSR, bs, SB3);
    stats_kernel<<<64, 256, 0, s2>>>(SB3, sums + 256);
    cudaEventRecord(evD, s2);
    cudaStreamWaitEvent(0, evD, 0);                 // join before z

    // z = noise*exp(bn(SB3)) + bn(SB2); also emits bf16 hi/lo split
    z_bn_kernel<<<3000, 256>>>(noise, SB2, SB3, sums, gm, bem, gs, bes, Z, ZHI, ZLO);

    // fork: decoder on s1 concurrent with apred on main (disjoint out regions)
    cudaEventRecord(evA, 0);
    cudaStreamWaitEvent(s1, evA, 0);
    gemm_kernel<DD, DD, 1><<<750, 256, 0, s1>>>(Z, Dw1, Db1, H1);
    gemm_kernel<DD, FIN_, 2><<<750, 256, 0, s1>>>(H1, Dw2, Db2, out);
    cudaEventRecord(evE, s1);

    dim3 grid((N_NODES + 127) / 128, (N_NODES + 127) / 128);
    apred_mma_kernel<<<grid, 256, APRED_SMEM>>>(ZHI, ZLO, out + (size_t)N_NODES * FIN_);
    cudaStreamWaitEvent(0, evE, 0);                 // final join
}